// round 12
// baseline (speedup 1.0000x reference)
#include <cuda_runtime.h>
#include <cuda_bf16.h>

#define T_LEN 1024
#define B_SZ  64
#define ALPHA_ 0.7f
#define GAMMA_ 0.2f
#define KEXP_  7.2134752f      // (1/GAMMA)*log2(e)  (domain scale K)
#define KINV_  0.13862944f     // 1/K = GAMMA*ln(2)
#define INF_S  7.2134752e9f    // K * 1e9 (scaled INF)
#define FULL_  0xffffffffu
#define NROUND 159             // 3*31 + 65 + 1

typedef unsigned long long ull;

__device__ float g_mse_b[B_SZ];
__device__ float g_sdtw[B_SZ];
__device__ float g_mse_total;
__device__ float g_dummy;

__device__ __forceinline__ float ex2(float x) {
    float r; asm("ex2.approx.ftz.f32 %0, %1;" : "=f"(r) : "f"(x)); return r;
}
__device__ __forceinline__ float lg2f_(float x) {
    float r; asm("lg2.approx.ftz.f32 %0, %1;" : "=f"(r) : "f"(x)); return r;
}
__device__ __forceinline__ ull pk(float lo, float hi) {
    ull r; asm("mov.b64 %0, {%1, %2};" : "=l"(r) : "f"(lo), "f"(hi)); return r;
}
__device__ __forceinline__ ull ffma2(ull a, ull b, ull c) {
    ull d; asm("fma.rn.f32x2 %0, %1, %2, %3;" : "=l"(d) : "l"(a), "l"(b), "l"(c));
    return d;
}

// Scaled-domain cell: val' = (Kd + mn') - lg2(1 + ex2(dm') + ex2(dmid')).
// No multiplies (K*GAMMA*ln2 == 1). One of the three diffs is exactly 0.
__device__ __forceinline__ float cellv(float Kd, float up, float lf, float dg) {
    float mn   = fminf(up, fminf(lf, dg));
    float mx   = fmaxf(up, fmaxf(lf, dg));
    float dsum = fmaf(3.f, mn, -((up + lf) + dg));
    float dm   = mn - mx;
    float dmid = dsum - dm;
    float s = (1.f + ex2(dm)) + ex2(dmid);
    return (Kd + mn) - lg2f_(s);
}

// K-scaled distance: Kd = x2K + y2K[j] + dot(P, tpK[j]) (tpK pre-scaled -2K)
__device__ __forceinline__ float distK(const ull* __restrict__ tpK,
                                       const float* __restrict__ y2K, int j,
                                       ull P0, ull P1, ull P2, ull P3, float x2K) {
    ull acc = ffma2(P0, tpK[j], pk(x2K, y2K[j]));
    acc = ffma2(P1, tpK[j + 1024], acc);
    acc = ffma2(P2, tpK[j + 2048], acc);
    acc = ffma2(P3, tpK[j + 3072], acc);
    float a, b;
    asm("mov.b64 {%0,%1},%2;" : "=f"(a), "=f"(b) : "l"(acc));
    return a + b;
}

// ---------------------------------------------------------------------------
// Soft-DTW, warp-shuffle skewed wavefront, chunk=16 / skew=3.
// 1024 threads = 32 warps; warp w owns rows [32w,32w+32); chunk m covers
// global steps k in [32w+16m, +16) and runs at round r = 3w+m, m in [0,65];
// 159 rounds. Boundary (row 32w-1) values for warp w come from warp w-1's
// chunks m+1 (round r-2, last slot) and m+2 (round r-1): 3-phase ring of
// 16 floats per warp per round. Lane 0's boundary value is pipelined via a
// register (predicated LDS one step ahead) -> ONE shfl per step.
// ---------------------------------------------------------------------------
__global__ __launch_bounds__(1024, 1)
void sdtw_kernel(const float* __restrict__ pred,
                 const float* __restrict__ target) {
    extern __shared__ char smraw[];
    ull*   tpK  = (ull*)smraw;                             // 4*1024 (32KB)
    float* y2K  = (float*)(smraw + 32768);                 // 1024
    float* ring = (float*)(smraw + 32768 + 4096);          // 3*32*16
    float* wred = (float*)(smraw + 32768 + 4096 + 6144);   // 32

    const int i = threadIdx.x;
    const int w = i >> 5;
    const int l = i & 31;
    const int b = blockIdx.x;

    const float4* pg = (const float4*)(pred + (size_t)b * T_LEN * 8);
    const float4* gg = (const float4*)(target + (size_t)b * T_LEN * 8);
    float4 p0 = pg[2 * i], p1 = pg[2 * i + 1];
    float4 t0 = gg[2 * i], t1 = gg[2 * i + 1];

    const float n2k = -2.f * KEXP_;
    tpK[i]        = pk(n2k * t0.x, n2k * t0.y);
    tpK[i + 1024] = pk(n2k * t0.z, n2k * t0.w);
    tpK[i + 2048] = pk(n2k * t1.x, n2k * t1.y);
    tpK[i + 3072] = pk(n2k * t1.z, n2k * t1.w);
    y2K[i] = KEXP_ * (t0.x*t0.x + t0.y*t0.y + t0.z*t0.z + t0.w*t0.w +
                      t1.x*t1.x + t1.y*t1.y + t1.z*t1.z + t1.w*t1.w);
    const float x2K = KEXP_ * (p0.x*p0.x + p0.y*p0.y + p0.z*p0.z + p0.w*p0.w +
                               p1.x*p1.x + p1.y*p1.y + p1.z*p1.z + p1.w*p1.w);
    const ull P0 = pk(p0.x, p0.y), P1 = pk(p0.z, p0.w);
    const ull P2 = pk(p1.x, p1.y), P3 = pk(p1.z, p1.w);

    // fused per-batch MSE partial
    {
        float dx, acc = 0.f;
        dx = p0.x - t0.x; acc = fmaf(dx, dx, acc);
        dx = p0.y - t0.y; acc = fmaf(dx, dx, acc);
        dx = p0.z - t0.z; acc = fmaf(dx, dx, acc);
        dx = p0.w - t0.w; acc = fmaf(dx, dx, acc);
        dx = p1.x - t1.x; acc = fmaf(dx, dx, acc);
        dx = p1.y - t1.y; acc = fmaf(dx, dx, acc);
        dx = p1.z - t1.z; acc = fmaf(dx, dx, acc);
        dx = p1.w - t1.w; acc = fmaf(dx, dx, acc);
#pragma unroll
        for (int o = 16; o; o >>= 1) acc += __shfl_xor_sync(FULL_, acc, o);
        if (l == 0) wred[w] = acc;
    }
    for (int idx = i; idx < 3 * 512; idx += 1024) ring[idx] = INF_S;
    if (i < 3 * 512 - 1024) ring[i + 1024] = INF_S;
    __syncthreads();
    if (i == 0) {
        float msum = 0.f;
#pragma unroll
        for (int q = 0; q < 32; ++q) msum += wred[q];
        g_mse_b[b] = msum;
    }

    float prev    = INF_S;
    float up_prev = (i == 0) ? 0.f : INF_S;  // diag source; 0 seeds cell (0,0)
    float lastv   = INF_S;
    const bool ld0 = (l == 0) && (w > 0);    // lane doing boundary loads

    for (int r = 0; r < NROUND; ++r) {
        const int m = r - 3 * w;
        if ((unsigned)m <= 65u) {
            float* wr = ring + (r % 3) * 512 + w * 16;
            const float* r1 = ring + ((r + 2) % 3) * 512 + (w - 1) * 16; // round r-1
            const float* r2 = ring + ((r + 1) % 3) * 512 + (w - 1) * 16; // round r-2

            // boundary register: value step o's lane-0 needs as `up`.
            // prime with o=0's value (warp w-1 chunk m+1, last slot, round r-2)
            float bn = INF_S;
            if (ld0) bn = r2[15];

            if (m >= 2 && m <= 63) {
                // interior: all lanes valid at every step
                const int jbase = 16 * m - l;
                const ull*   tpp = tpK + jbase;
                const float* yp  = y2K + jbase;

                float dc0 = distK(tpp, yp, 0, P0, P1, P2, P3, x2K);
                float dc1 = distK(tpp, yp, 1, P0, P1, P2, P3, x2K);
                float dc2 = distK(tpp, yp, 2, P0, P1, P2, P3, x2K);
                float dc3 = distK(tpp, yp, 3, P0, P1, P2, P3, x2K);

#pragma unroll
                for (int g = 0; g < 4; ++g) {
                    float dn0 = 0.f, dn1 = 0.f, dn2 = 0.f, dn3 = 0.f;
                    if (g < 3) {  // prefetch next group's distances (off-chain)
                        const int q = 4 * g + 4;
                        dn0 = distK(tpp, yp, q + 0, P0, P1, P2, P3, x2K);
                        dn1 = distK(tpp, yp, q + 1, P0, P1, P2, P3, x2K);
                        dn2 = distK(tpp, yp, q + 2, P0, P1, P2, P3, x2K);
                        dn3 = distK(tpp, yp, q + 3, P0, P1, P2, P3, x2K);
                    }
#pragma unroll
                    for (int q = 0; q < 4; ++q) {
                        const int o = 4 * g + q;
                        float d = (q == 0) ? dc0 : (q == 1) ? dc1 : (q == 2) ? dc2 : dc3;
                        float up = __shfl_up_sync(FULL_, prev, 1);
                        if (l == 0) up = bn;
                        if (ld0) bn = r1[o];      // boundary for step o+1 (off-chain)
                        float v = cellv(d, up, prev, up_prev);
                        up_prev = up; prev = v;
                        if (l == 31) wr[o] = v;
                    }
                    dc0 = dn0; dc1 = dn1; dc2 = dn2; dc3 = dn3;
                }
            } else {
                // edge chunks m in {0,1,64,65}: per-lane validity, masked index
#pragma unroll 4
                for (int o = 0; o < 16; ++o) {
                    float up = __shfl_up_sync(FULL_, prev, 1);
                    if (l == 0) up = bn;
                    if (ld0) bn = r1[o];
                    int j = 16 * m + o - l;
                    bool valid = (unsigned)j < (unsigned)T_LEN;
                    int jc = j & (T_LEN - 1);
                    float d = distK(tpK, y2K, jc, P0, P1, P2, P3, x2K);
                    float v = valid ? cellv(d, up, prev, up_prev) : INF_S;
                    up_prev = up; prev = v;
                    if (valid) lastv = v;
                    if (l == 31) wr[o] = v;
                }
            }
        }
        __syncthreads();
    }

    if (i == T_LEN - 1) g_sdtw[b] = lastv * KINV_;   // unscale R[T-1][T-1]
}

// ---------------------------------------------------------------------------
// Harness issues 2 pre-launches; 3 dummies put sdtw at global launch #5
// (ncu -s 5 -c 1 target).
__global__ void dummy_kernel(int v) { if (threadIdx.x == 1024) g_dummy = (float)v; }

__global__ void bridge_kernel() {   // reduce 64 mse partials
    const int t = threadIdx.x;  // 32
    float m = g_mse_b[t] + g_mse_b[t + 32];
#pragma unroll
    for (int o = 16; o; o >>= 1) m += __shfl_xor_sync(FULL_, m, o);
    if (t == 0) g_mse_total = m;
}

__global__ void final_kernel(float* __restrict__ out) {
    const int t = threadIdx.x;  // 64
    float sd = g_sdtw[t];
#pragma unroll
    for (int o = 16; o; o >>= 1) sd += __shfl_xor_sync(FULL_, sd, o);
    __shared__ float ss_[2];
    if ((t & 31) == 0) ss_[t >> 5] = sd;
    __syncthreads();
    if (t == 0) {
        float mse  = g_mse_total / (float)(B_SZ * T_LEN * 8);
        float sdtw = (ss_[0] + ss_[1]) / (float)B_SZ;
        out[0] = ALPHA_ * mse + (1.0f - ALPHA_) * sdtw;
    }
}

// ---------------------------------------------------------------------------
extern "C" void kernel_launch(void* const* d_in, const int* in_sizes, int n_in,
                              void* d_out, int out_size) {
    const float* pred   = (const float*)d_in[0];
    const float* target = (const float*)d_in[1];
    float* out = (float*)d_out;

    const int smem = 32768 + 4096 + 6144 + 128;  // 43136 bytes
    cudaFuncSetAttribute(sdtw_kernel,
                         cudaFuncAttributeMaxDynamicSharedMemorySize, smem);

    dummy_kernel<<<1, 32>>>(0);
    dummy_kernel<<<1, 32>>>(1);
    dummy_kernel<<<1, 32>>>(2);
    sdtw_kernel<<<B_SZ, 1024, smem>>>(pred, target);
    bridge_kernel<<<1, 32>>>();
    final_kernel<<<1, 64>>>(out);
}

// round 13
// speedup vs baseline: 1.1716x; 1.1716x over previous
#include <cuda_runtime.h>
#include <cuda_bf16.h>

#define T_LEN 1024
#define B_SZ  64
#define ALPHA_ 0.7f
#define GAMMA_ 0.2f
#define KEXP_  7.2134752f      // (1/GAMMA)*log2(e)  (domain scale K)
#define KINV_  0.13862944f     // 1/K = GAMMA*ln(2)
#define INF_S  7.2134752e9f    // K * 1e9 (scaled INF)
#define FULL_  0xffffffffu
#define RING_D 8               // ring depth in chunks (of 16 floats)
#define NCHUNK 66              // 1056 / 16 chunks per warp

typedef unsigned long long ull;

__device__ float g_mse_b[B_SZ];
__device__ float g_sdtw[B_SZ];
__device__ float g_mse_total;
__device__ float g_dummy;

__device__ __forceinline__ float ex2(float x) {
    float r; asm("ex2.approx.ftz.f32 %0, %1;" : "=f"(r) : "f"(x)); return r;
}
__device__ __forceinline__ float lg2f_(float x) {
    float r; asm("lg2.approx.ftz.f32 %0, %1;" : "=f"(r) : "f"(x)); return r;
}
__device__ __forceinline__ ull pk(float lo, float hi) {
    ull r; asm("mov.b64 %0, {%1, %2};" : "=l"(r) : "f"(lo), "f"(hi)); return r;
}
__device__ __forceinline__ ull ffma2(ull a, ull b, ull c) {
    ull d; asm("fma.rn.f32x2 %0, %1, %2, %3;" : "=l"(d) : "l"(a), "l"(b), "l"(c));
    return d;
}
__device__ __forceinline__ int ldacq(unsigned a) {
    int v; asm volatile("ld.acquire.cta.shared.b32 %0, [%1];"
                        : "=r"(v) : "r"(a) : "memory");
    return v;
}
__device__ __forceinline__ void strel(unsigned a, int v) {
    asm volatile("st.release.cta.shared.b32 [%0], %1;" :: "r"(a), "r"(v) : "memory");
}

// Scaled-domain cell: val' = (Kd + mn') - lg2(1 + ex2(dm') + ex2(dmid')).
// No multiplies (K*GAMMA*ln2 == 1). One of the three diffs is exactly 0.
__device__ __forceinline__ float cellv(float Kd, float up, float lf, float dg) {
    float mn   = fminf(up, fminf(lf, dg));
    float mx   = fmaxf(up, fmaxf(lf, dg));
    float dsum = fmaf(3.f, mn, -((up + lf) + dg));
    float dm   = mn - mx;
    float dmid = dsum - dm;
    float s = (1.f + ex2(dm)) + ex2(dmid);
    return (Kd + mn) - lg2f_(s);
}

// K-scaled distance: Kd = x2K + y2K[j] + dot(P, tpK[j]) (tpK pre-scaled -2K)
__device__ __forceinline__ float distK(const ull* __restrict__ tpK,
                                       const float* __restrict__ y2K, int j,
                                       ull P0, ull P1, ull P2, ull P3, float x2K) {
    ull acc = ffma2(P0, tpK[j], pk(x2K, y2K[j]));
    acc = ffma2(P1, tpK[j + 1024], acc);
    acc = ffma2(P2, tpK[j + 2048], acc);
    acc = ffma2(P3, tpK[j + 3072], acc);
    float a, b;
    asm("mov.b64 {%0,%1},%2;" : "=f"(a), "=f"(b) : "l"(acc));
    return a + b;
}

// ---------------------------------------------------------------------------
// Soft-DTW, SELF-TIMED warp pipeline (no per-round __syncthreads).
// 1024 threads = 32 warps; warp w owns rows [32w,32w+32); chunk m covers its
// local steps [16m, 16m+16) (global k = 32w + 16m + o); 66 chunks per warp.
// Warp w chunk m needs warp w-1's chunk m+1 slot 15 (prime) and chunk m+2
// slots 0..14 (per-step) -> wait until prod[w-1] >= m+3 (flag handshake with
// ld.acquire / st.release, ring depth RING_D chunks). Producer throttles on
// cons[w+1] so ring slots are never overwritten before consumption.
// Serial chain per step: shfl_up -> cellv; boundary bn pipelined off-chain.
// ---------------------------------------------------------------------------
__global__ __launch_bounds__(1024, 1)
void sdtw_kernel(const float* __restrict__ pred,
                 const float* __restrict__ target) {
    extern __shared__ char smraw[];
    ull*   tpK  = (ull*)smraw;                             // 4*1024 (32KB)
    float* y2K  = (float*)(smraw + 32768);                 // 1024
    float* ring = (float*)(smraw + 32768 + 4096);          // 32*RING_D*16 (16KB)
    int*   prod = (int*)(smraw + 32768 + 4096 + 16384);    // 32
    int*   cons = prod + 32;                               // 32
    float* wred = (float*)(cons + 32);                     // 32

    const int i = threadIdx.x;
    const int w = i >> 5;
    const int l = i & 31;
    const int b = blockIdx.x;

    const float4* pg = (const float4*)(pred + (size_t)b * T_LEN * 8);
    const float4* gg = (const float4*)(target + (size_t)b * T_LEN * 8);
    float4 p0 = pg[2 * i], p1 = pg[2 * i + 1];
    float4 t0 = gg[2 * i], t1 = gg[2 * i + 1];

    const float n2k = -2.f * KEXP_;
    tpK[i]        = pk(n2k * t0.x, n2k * t0.y);
    tpK[i + 1024] = pk(n2k * t0.z, n2k * t0.w);
    tpK[i + 2048] = pk(n2k * t1.x, n2k * t1.y);
    tpK[i + 3072] = pk(n2k * t1.z, n2k * t1.w);
    y2K[i] = KEXP_ * (t0.x*t0.x + t0.y*t0.y + t0.z*t0.z + t0.w*t0.w +
                      t1.x*t1.x + t1.y*t1.y + t1.z*t1.z + t1.w*t1.w);
    const float x2K = KEXP_ * (p0.x*p0.x + p0.y*p0.y + p0.z*p0.z + p0.w*p0.w +
                               p1.x*p1.x + p1.y*p1.y + p1.z*p1.z + p1.w*p1.w);
    const ull P0 = pk(p0.x, p0.y), P1 = pk(p0.z, p0.w);
    const ull P2 = pk(p1.x, p1.y), P3 = pk(p1.z, p1.w);

    // fused per-batch MSE partial
    {
        float dx, acc = 0.f;
        dx = p0.x - t0.x; acc = fmaf(dx, dx, acc);
        dx = p0.y - t0.y; acc = fmaf(dx, dx, acc);
        dx = p0.z - t0.z; acc = fmaf(dx, dx, acc);
        dx = p0.w - t0.w; acc = fmaf(dx, dx, acc);
        dx = p1.x - t1.x; acc = fmaf(dx, dx, acc);
        dx = p1.y - t1.y; acc = fmaf(dx, dx, acc);
        dx = p1.z - t1.z; acc = fmaf(dx, dx, acc);
        dx = p1.w - t1.w; acc = fmaf(dx, dx, acc);
#pragma unroll
        for (int o = 16; o; o >>= 1) acc += __shfl_xor_sync(FULL_, acc, o);
        if (l == 0) wred[w] = acc;
    }
    // init ring (finite values only) + flags
    for (int idx = i; idx < 32 * RING_D * 16; idx += 1024) ring[idx] = INF_S;
    if (i < 32) { prod[i] = 0; cons[i] = 0; }
    __syncthreads();
    if (i == 0) {
        float msum = 0.f;
#pragma unroll
        for (int q = 0; q < 32; ++q) msum += wred[q];
        g_mse_b[b] = msum;
    }

    // flag addresses
    const unsigned prodPrevA = (unsigned)__cvta_generic_to_shared(prod + ((w > 0) ? w - 1 : 0));
    const unsigned consNextA = (unsigned)__cvta_generic_to_shared(cons + ((w < 31) ? w + 1 : 31));
    const unsigned prodSelfA = (unsigned)__cvta_generic_to_shared(prod + w);
    const unsigned consSelfA = (unsigned)__cvta_generic_to_shared(cons + w);

    float* ringW = ring + w * (RING_D * 16);
    const float* ringP = ring + ((w > 0) ? w - 1 : 0) * (RING_D * 16);

    float prev    = INF_S;
    float up_prev = (i == 0) ? 0.f : INF_S;  // diag source; 0 seeds cell (0,0)
    float lastv   = INF_S;
    const bool ld0 = (l == 0) && (w > 0);

    for (int m = 0; m < NCHUNK; ++m) {
        // consumer wait: need producer chunks m+1 (prime) and m+2 (steps)
        if (w > 0 && m <= 63) {
            while (ldacq(prodPrevA) < m + 3) { }
        }
        // producer throttle: don't overwrite ring slot before consumer read it
        if (w < 31 && m >= RING_D) {
            const int need = m - RING_D + 1;
            while (ldacq(consNextA) < need) { }
        }

        float* wr = ringW + (m & (RING_D - 1)) * 16;
        const float* rp1 = ringP + ((m + 1) & (RING_D - 1)) * 16;
        const float* rp2 = ringP + ((m + 2) & (RING_D - 1)) * 16;

        float bn = INF_S;
        if (ld0) bn = rp1[15];          // boundary for step o=0

        if (m >= 2 && m <= 63) {
            // interior chunk: all lanes valid at every step
            const int jbase = 16 * m - l;
            const ull*   tpp = tpK + jbase;
            const float* yp  = y2K + jbase;

            float dc0 = distK(tpp, yp, 0, P0, P1, P2, P3, x2K);
            float dc1 = distK(tpp, yp, 1, P0, P1, P2, P3, x2K);
            float dc2 = distK(tpp, yp, 2, P0, P1, P2, P3, x2K);
            float dc3 = distK(tpp, yp, 3, P0, P1, P2, P3, x2K);

#pragma unroll
            for (int g = 0; g < 4; ++g) {
                float dn0 = 0.f, dn1 = 0.f, dn2 = 0.f, dn3 = 0.f;
                if (g < 3) {  // prefetch next group's distances (off-chain)
                    const int q = 4 * g + 4;
                    dn0 = distK(tpp, yp, q + 0, P0, P1, P2, P3, x2K);
                    dn1 = distK(tpp, yp, q + 1, P0, P1, P2, P3, x2K);
                    dn2 = distK(tpp, yp, q + 2, P0, P1, P2, P3, x2K);
                    dn3 = distK(tpp, yp, q + 3, P0, P1, P2, P3, x2K);
                }
#pragma unroll
                for (int q = 0; q < 4; ++q) {
                    const int o = 4 * g + q;
                    float d = (q == 0) ? dc0 : (q == 1) ? dc1 : (q == 2) ? dc2 : dc3;
                    float up = __shfl_up_sync(FULL_, prev, 1);
                    if (l == 0) up = bn;
                    if (ld0) bn = rp2[o];     // boundary for step o+1 (off-chain)
                    float v = cellv(d, up, prev, up_prev);
                    up_prev = up; prev = v;
                    if (l == 31) wr[o] = v;
                }
                dc0 = dn0; dc1 = dn1; dc2 = dn2; dc3 = dn3;
            }
        } else {
            // edge chunks m in {0,1,64,65}: per-lane validity, masked index
#pragma unroll 4
            for (int o = 0; o < 16; ++o) {
                float up = __shfl_up_sync(FULL_, prev, 1);
                if (l == 0) up = bn;
                if (ld0) bn = rp2[o];
                int j = 16 * m + o - l;
                bool valid = (unsigned)j < (unsigned)T_LEN;
                int jc = j & (T_LEN - 1);
                float d = distK(tpK, y2K, jc, P0, P1, P2, P3, x2K);
                float v = valid ? cellv(d, up, prev, up_prev) : INF_S;
                up_prev = up; prev = v;
                if (valid) lastv = v;
                if (l == 31) wr[o] = v;
            }
        }

        // publish: lane 31's ring stores ordered by release; lane 0's ring
        // reads ordered by release on cons.
        if (l == 31) strel(prodSelfA, m + 1);
        else if (l == 0) strel(consSelfA, m + 1);
    }

    if (i == T_LEN - 1) g_sdtw[b] = lastv * KINV_;   // unscale R[T-1][T-1]
}

// ---------------------------------------------------------------------------
// Harness issues 2 pre-launches; 3 dummies put sdtw at global launch #5
// (ncu -s 5 -c 1 target).
__global__ void dummy_kernel(int v) { if (threadIdx.x == 1024) g_dummy = (float)v; }

__global__ void bridge_kernel() {   // reduce 64 mse partials
    const int t = threadIdx.x;  // 32
    float m = g_mse_b[t] + g_mse_b[t + 32];
#pragma unroll
    for (int o = 16; o; o >>= 1) m += __shfl_xor_sync(FULL_, m, o);
    if (t == 0) g_mse_total = m;
}

__global__ void final_kernel(float* __restrict__ out) {
    const int t = threadIdx.x;  // 64
    float sd = g_sdtw[t];
#pragma unroll
    for (int o = 16; o; o >>= 1) sd += __shfl_xor_sync(FULL_, sd, o);
    __shared__ float ss_[2];
    if ((t & 31) == 0) ss_[t >> 5] = sd;
    __syncthreads();
    if (t == 0) {
        float mse  = g_mse_total / (float)(B_SZ * T_LEN * 8);
        float sdtw = (ss_[0] + ss_[1]) / (float)B_SZ;
        out[0] = ALPHA_ * mse + (1.0f - ALPHA_) * sdtw;
    }
}

// ---------------------------------------------------------------------------
extern "C" void kernel_launch(void* const* d_in, const int* in_sizes, int n_in,
                              void* d_out, int out_size) {
    const float* pred   = (const float*)d_in[0];
    const float* target = (const float*)d_in[1];
    float* out = (float*)d_out;

    const int smem = 32768 + 4096 + 16384 + 256 + 128;  // 53632 bytes
    cudaFuncSetAttribute(sdtw_kernel,
                         cudaFuncAttributeMaxDynamicSharedMemorySize, smem);

    dummy_kernel<<<1, 32>>>(0);
    dummy_kernel<<<1, 32>>>(1);
    dummy_kernel<<<1, 32>>>(2);
    sdtw_kernel<<<B_SZ, 1024, smem>>>(pred, target);
    bridge_kernel<<<1, 32>>>();
    final_kernel<<<1, 64>>>(out);
}